// round 6
// baseline (speedup 1.0000x reference)
#include <cuda_runtime.h>
#include <cuda_bf16.h>

// ---------------------------------------------------------------------------
// Actor network: GRU (H=256) over V=20 vehicle slots, then 4-layer MLP + tanh.
// B=16384, F=15. All fp32. Strategy: packed f32x2 FFMA everywhere (2x fp32
// rate on sm_103a), h resident in SMEM across all 20 GRU steps, transposed
// (k-major) weights for coalesced f32x2 operand loads.
// No host API calls in kernel_launch except kernel launches (capture-safe).
// ---------------------------------------------------------------------------

#define BATCH 16384
typedef unsigned long long u64;

// Scratch (device globals: allocation-free per harness rules)
__device__ __align__(16) float g_WihT[15 * 768];
__device__ __align__(16) float g_WhhT[256 * 768];
__device__ __align__(16) float g_brz[512];
__device__ __align__(16) float g_W1T[271 * 1024];
__device__ __align__(16) float g_W2T[1024 * 1024];
__device__ __align__(16) float g_W3T[1024 * 512];
__device__ __align__(16) float g_W4T[512 * 256];
__device__ __align__(16) float g_xin[BATCH * 271];   // [state15 | h256]
__device__ __align__(16) float g_x1[BATCH * 1024];
__device__ __align__(16) float g_x2[BATCH * 1024];
__device__ __align__(16) float g_x3[BATCH * 512];
__device__ __align__(16) float g_x4[BATCH * 256];

// ---- packed f32x2 helpers (FFMA2 path; ptxas never emits this from C++) ----
__device__ __forceinline__ u64 pk2(float a) {
    u64 r; asm("mov.b64 %0, {%1, %1};" : "=l"(r) : "f"(a)); return r;
}
__device__ __forceinline__ void fma2(u64& d, u64 a, u64 b) {
    asm("fma.rn.f32x2 %0, %1, %2, %0;" : "+l"(d) : "l"(a), "l"(b));
}
__device__ __forceinline__ float2 unpk(u64 v) {
    float x, y; asm("mov.b64 {%0, %1}, %2;" : "=f"(x), "=f"(y) : "l"(v));
    float2 f; f.x = x; f.y = y; return f;
}
__device__ __forceinline__ float sigf(float x) {
    return 1.f / (1.f + __expf(-x));
}

// ---------------------------------------------------------------------------
// Prep: transpose all weights to k-major, combine r/z biases, copy state[:,0,:]
// into the MLP input buffer. Tiny one-time cost per replay.
// ---------------------------------------------------------------------------
__global__ void prep_kernel(const float* __restrict__ state,
                            const float* __restrict__ W_ih,
                            const float* __restrict__ W_hh,
                            const float* __restrict__ b_ih,
                            const float* __restrict__ b_hh,
                            const float* __restrict__ W1,
                            const float* __restrict__ W2,
                            const float* __restrict__ W3,
                            const float* __restrict__ W4) {
    long i = (long)blockIdx.x * blockDim.x + threadIdx.x;
    long stride = (long)gridDim.x * blockDim.x;
    for (long x = i; x < 15L * 768; x += stride) {
        long k = x / 768, jj = x - k * 768;
        g_WihT[x] = W_ih[jj * 15 + k];
    }
    for (long x = i; x < 256L * 768; x += stride) {
        long k = x / 768, jj = x - k * 768;
        g_WhhT[x] = W_hh[jj * 256 + k];
    }
    for (long x = i; x < 512; x += stride) g_brz[x] = b_ih[x] + b_hh[x];
    for (long x = i; x < 271L * 1024; x += stride) {
        long k = x >> 10, jj = x & 1023;
        g_W1T[x] = W1[jj * 271 + k];
    }
    for (long x = i; x < 1024L * 1024; x += stride) {
        long k = x >> 10, jj = x & 1023;
        g_W2T[x] = W2[jj * 1024 + k];
    }
    for (long x = i; x < 1024L * 512; x += stride) {
        long k = x / 512, jj = x - k * 512;
        g_W3T[x] = W3[jj * 1024 + k];
    }
    for (long x = i; x < 512L * 256; x += stride) {
        long k = x >> 8, jj = x & 255;
        g_W4T[x] = W4[jj * 512 + k];
    }
    for (long x = i; x < (long)BATCH * 15; x += stride) {
        long b = x / 15; long f = x - b * 15;
        g_xin[b * 271 + f] = state[b * 300 + f];  // state[b][0][f]
    }
}

// ---------------------------------------------------------------------------
// GRU: 32 rows per CTA, h in SMEM for all 20 steps. 512 threads:
//   jp = tid&127 -> cols (2jp, 2jp+1); ty = tid>>7 -> rows ty*8..ty*8+7.
// Per thread: 8 rows x {r,z,xn,hn} f32x2 accumulators (xn kept separate from
// hn because n = tanh(xn + r*hn)).
// ---------------------------------------------------------------------------
__global__ __launch_bounds__(512, 1) void gru_kernel(
    const float* __restrict__ state,
    const float* __restrict__ b_ih,
    const float* __restrict__ b_hh) {
    __shared__ float h_s[32][256];
    __shared__ float s_s[32][15];
    int tid = threadIdx.x;
    int jp = tid & 127; int j = jp << 1;
    int ty = tid >> 7;  int r0 = ty << 3;
    long b0 = (long)blockIdx.x << 5;

    for (int idx = tid; idx < 32 * 256; idx += 512) ((float*)h_s)[idx] = 0.f;

    u64 bias_r  = *(const u64*)(g_brz + j);
    u64 bias_z  = *(const u64*)(g_brz + 256 + j);
    u64 bias_xn = *(const u64*)(b_ih + 512 + j);
    u64 bias_hn = *(const u64*)(b_hh + 512 + j);

    for (int t = 0; t < 20; t++) {
        __syncthreads();   // h_s (and prev s_s use) stable
        for (int idx = tid; idx < 32 * 15; idx += 512) {
            int rr = idx / 15, ff = idx - rr * 15;
            s_s[rr][ff] = state[(b0 + rr) * 300 + t * 15 + ff];
        }
        __syncthreads();

        u64 accr[8], accz[8], accxn[8], acchn[8];
        #pragma unroll
        for (int i = 0; i < 8; i++) {
            accr[i] = bias_r; accz[i] = bias_z;
            accxn[i] = bias_xn; acchn[i] = bias_hn;
        }
        // input-side: K=15
        #pragma unroll 3
        for (int k = 0; k < 15; k++) {
            u64 wr = *(const u64*)(g_WihT + k * 768 + j);
            u64 wz = *(const u64*)(g_WihT + k * 768 + 256 + j);
            u64 wn = *(const u64*)(g_WihT + k * 768 + 512 + j);
            #pragma unroll
            for (int i = 0; i < 8; i++) {
                u64 aa = pk2(s_s[r0 + i][k]);
                fma2(accr[i], aa, wr);
                fma2(accz[i], aa, wz);
                fma2(accxn[i], aa, wn);
            }
        }
        // hidden-side: K=256
        #pragma unroll 2
        for (int k = 0; k < 256; k++) {
            u64 wr = *(const u64*)(g_WhhT + k * 768 + j);
            u64 wz = *(const u64*)(g_WhhT + k * 768 + 256 + j);
            u64 wn = *(const u64*)(g_WhhT + k * 768 + 512 + j);
            #pragma unroll
            for (int i = 0; i < 8; i++) {
                u64 aa = pk2(h_s[r0 + i][k]);
                fma2(accr[i], aa, wr);
                fma2(accz[i], aa, wz);
                fma2(acchn[i], aa, wn);
            }
        }
        __syncthreads();   // all h_s reads done before overwrite
        #pragma unroll
        for (int i = 0; i < 8; i++) {
            float2 fr = unpk(accr[i]),  fz = unpk(accz[i]);
            float2 fxn = unpk(accxn[i]), fhn = unpk(acchn[i]);
            float h0 = h_s[r0 + i][j], h1 = h_s[r0 + i][j + 1];
            float rr0 = sigf(fr.x), rr1 = sigf(fr.y);
            float zz0 = sigf(fz.x), zz1 = sigf(fz.y);
            float nn0 = tanhf(fxn.x + rr0 * fhn.x);
            float nn1 = tanhf(fxn.y + rr1 * fhn.y);
            h_s[r0 + i][j]     = (1.f - zz0) * nn0 + zz0 * h0;
            h_s[r0 + i][j + 1] = (1.f - zz1) * nn1 + zz1 * h1;
        }
    }
    __syncthreads();
    for (int idx = tid; idx < 32 * 256; idx += 512) {
        int rr = idx >> 8, cc = idx & 255;
        g_xin[(b0 + rr) * 271 + 15 + cc] = h_s[rr][cc];
    }
}

// ---------------------------------------------------------------------------
// Generic MLP layer: Y[M,N] = act(X[M,K] @ WT + bias). CTA tile 64 rows x 256
// cols; 512 threads: tx=tid&31 -> 8 cols each, ty=tid>>5 -> 4 rows each.
// K streamed through SMEM in 128-wide chunks. Weight/IO pointers resolved
// from device globals via template parameterization (no host symbol lookup).
// ---------------------------------------------------------------------------
__device__ __forceinline__ void mlp_body(
    const float* __restrict__ X, int ldx, int K,
    const float* __restrict__ WT, const float* __restrict__ bias,
    float* __restrict__ Y, int N, int do_relu) {
    __shared__ float x_s[64][128];
    int tid = threadIdx.x;
    int tx = tid & 31, ty = tid >> 5;
    int c0 = blockIdx.y * 256 + tx * 8;
    long m0 = (long)blockIdx.x * 64;

    ulonglong2 ba = *(const ulonglong2*)(bias + c0);
    ulonglong2 bb = *(const ulonglong2*)(bias + c0 + 4);
    u64 acc[4][4];
    #pragma unroll
    for (int i = 0; i < 4; i++) {
        acc[i][0] = ba.x; acc[i][1] = ba.y; acc[i][2] = bb.x; acc[i][3] = bb.y;
    }

    for (int kk = 0; kk < K; kk += 128) {
        int kc = min(128, K - kk);
        __syncthreads();
        for (int idx = tid; idx < 64 * 128; idx += 512) {
            int rr = idx >> 7, k = idx & 127;
            if (k < kc) x_s[rr][k] = X[(m0 + rr) * ldx + kk + k];
        }
        __syncthreads();
        const float* wbase = WT + (size_t)kk * N + c0;
        #pragma unroll 4
        for (int k = 0; k < kc; k++) {
            ulonglong2 wa = *(const ulonglong2*)(wbase + (size_t)k * N);
            ulonglong2 wb = *(const ulonglong2*)(wbase + (size_t)k * N + 4);
            #pragma unroll
            for (int i = 0; i < 4; i++) {
                u64 aa = pk2(x_s[ty * 4 + i][k]);
                fma2(acc[i][0], aa, wa.x);
                fma2(acc[i][1], aa, wa.y);
                fma2(acc[i][2], aa, wb.x);
                fma2(acc[i][3], aa, wb.y);
            }
        }
    }
    #pragma unroll
    for (int i = 0; i < 4; i++) {
        long row = m0 + ty * 4 + i;
        #pragma unroll
        for (int q = 0; q < 4; q++) {
            float2 v = unpk(acc[i][q]);
            if (do_relu) { v.x = fmaxf(v.x, 0.f); v.y = fmaxf(v.y, 0.f); }
            *(float2*)(Y + row * N + c0 + 2 * q) = v;
        }
    }
}

__global__ __launch_bounds__(512, 1) void mlp1_kernel(const float* __restrict__ b1) {
    mlp_body(g_xin, 271, 271, g_W1T, b1, g_x1, 1024, 1);
}
__global__ __launch_bounds__(512, 1) void mlp2_kernel(const float* __restrict__ b2) {
    mlp_body(g_x1, 1024, 1024, g_W2T, b2, g_x2, 1024, 1);
}
__global__ __launch_bounds__(512, 1) void mlp3_kernel(const float* __restrict__ b3) {
    mlp_body(g_x2, 1024, 1024, g_W3T, b3, g_x3, 512, 1);
}
__global__ __launch_bounds__(512, 1) void mlp4_kernel(const float* __restrict__ b4) {
    mlp_body(g_x3, 512, 512, g_W4T, b4, g_x4, 256, 1);
}

// ---------------------------------------------------------------------------
// Head: out[b] = tanh(dot(x4[b], Wp) + bp). One warp per row.
// ---------------------------------------------------------------------------
__global__ void head_kernel(const float* __restrict__ Wp,
                            const float* __restrict__ bp,
                            float* __restrict__ out) {
    __shared__ float wp_s[256];
    int tid = threadIdx.x;
    if (tid < 256) wp_s[tid] = Wp[tid];
    __syncthreads();
    int warp = tid >> 5, lane = tid & 31;
    long b = (long)blockIdx.x * 8 + warp;
    float s = 0.f;
    #pragma unroll
    for (int i = 0; i < 8; i++) {
        int c = lane + 32 * i;
        s += g_x4[b * 256 + c] * wp_s[c];
    }
    #pragma unroll
    for (int o = 16; o; o >>= 1) s += __shfl_xor_sync(0xFFFFFFFFu, s, o);
    if (lane == 0) out[b] = tanhf(s + bp[0]);
}

// ---------------------------------------------------------------------------
extern "C" void kernel_launch(void* const* d_in, const int* in_sizes, int n_in,
                              void* d_out, int out_size) {
    const float* state = (const float*)d_in[0];
    const float* W_ih  = (const float*)d_in[1];
    const float* W_hh  = (const float*)d_in[2];
    const float* b_ih  = (const float*)d_in[3];
    const float* b_hh  = (const float*)d_in[4];
    const float* W1    = (const float*)d_in[5];
    const float* b1    = (const float*)d_in[6];
    const float* W2    = (const float*)d_in[7];
    const float* b2    = (const float*)d_in[8];
    const float* W3    = (const float*)d_in[9];
    const float* b3    = (const float*)d_in[10];
    const float* W4    = (const float*)d_in[11];
    const float* b4    = (const float*)d_in[12];
    const float* Wp    = (const float*)d_in[13];
    const float* bp    = (const float*)d_in[14];
    float* out = (float*)d_out;

    prep_kernel<<<2048, 256>>>(state, W_ih, W_hh, b_ih, b_hh, W1, W2, W3, W4);
    gru_kernel<<<BATCH / 32, 512>>>(state, b_ih, b_hh);
    mlp1_kernel<<<dim3(BATCH / 64, 4), 512>>>(b1);
    mlp2_kernel<<<dim3(BATCH / 64, 4), 512>>>(b2);
    mlp3_kernel<<<dim3(BATCH / 64, 2), 512>>>(b3);
    mlp4_kernel<<<dim3(BATCH / 64, 1), 512>>>(b4);
    head_kernel<<<BATCH / 8, 256>>>(Wp, bp, out);
}

// round 7
// speedup vs baseline: 1.1951x; 1.1951x over previous
#include <cuda_runtime.h>
#include <cuda_bf16.h>

// ---------------------------------------------------------------------------
// Actor: GRU (H=256) over V=20 steps + 4-layer MLP + tanh head. B=16384, F=15.
// f32x2 packed-FFMA design, restructured for FMA-pipe boundedness:
//  - activations loaded from SMEM as 64-bit broadcast pairs (k-pairs)
//  - MLP: 128x256 CTA tile, 8x8 per-thread tile (64 f32x2 accumulators)
//  - GRU: h resident in SMEM for all 20 steps; W_hh streamed from L2
// ---------------------------------------------------------------------------

#define BATCH 16384
typedef unsigned long long u64;

// Padded sizes
#define XIN_LD 272              // [state15 | h256 | pad1]
#define K1PAD 320               // mlp1 K padded to 5x64

__device__ __align__(16) float g_WihT[15 * 768];
__device__ __align__(16) float g_WhhT[256 * 768];
__device__ __align__(16) float g_brz[512];
__device__ __align__(16) float g_W1T[K1PAD * 1024];
__device__ __align__(16) float g_W2T[1024 * 1024];
__device__ __align__(16) float g_W3T[1024 * 512];
__device__ __align__(16) float g_W4T[512 * 256];
__device__ __align__(16) float g_xin[BATCH * XIN_LD];
__device__ __align__(16) float g_x1[BATCH * 1024];
__device__ __align__(16) float g_x2[BATCH * 1024];
__device__ __align__(16) float g_x3[BATCH * 512];
__device__ __align__(16) float g_x4[BATCH * 256];

// ---- packed f32x2 helpers ----
__device__ __forceinline__ u64 pk2(float a) {
    u64 r; asm("mov.b64 %0, {%1, %1};" : "=l"(r) : "f"(a)); return r;
}
__device__ __forceinline__ void fma2(u64& d, u64 a, u64 b) {
    asm("fma.rn.f32x2 %0, %1, %2, %0;" : "+l"(d) : "l"(a), "l"(b));
}
__device__ __forceinline__ float2 unpk(u64 v) {
    float x, y; asm("mov.b64 {%0, %1}, %2;" : "=f"(x), "=f"(y) : "l"(v));
    float2 f; f.x = x; f.y = y; return f;
}
__device__ __forceinline__ float sigf(float x) {
    return 1.f / (1.f + __expf(-x));
}

// ---------------------------------------------------------------------------
// Prep: k-major weight transposes (+ zero padding), combined r/z biases,
// state[:,0,:] into the MLP input buffer.
// ---------------------------------------------------------------------------
__global__ void prep_kernel(const float* __restrict__ state,
                            const float* __restrict__ W_ih,
                            const float* __restrict__ W_hh,
                            const float* __restrict__ b_ih,
                            const float* __restrict__ b_hh,
                            const float* __restrict__ W1,
                            const float* __restrict__ W2,
                            const float* __restrict__ W3,
                            const float* __restrict__ W4) {
    long i = (long)blockIdx.x * blockDim.x + threadIdx.x;
    long stride = (long)gridDim.x * blockDim.x;
    for (long x = i; x < 15L * 768; x += stride) {
        long k = x / 768, jj = x - k * 768;
        g_WihT[x] = W_ih[jj * 15 + k];
    }
    for (long x = i; x < 256L * 768; x += stride) {
        long k = x / 768, jj = x - k * 768;
        g_WhhT[x] = W_hh[jj * 256 + k];
    }
    for (long x = i; x < 512; x += stride) g_brz[x] = b_ih[x] + b_hh[x];
    for (long x = i; x < (long)K1PAD * 1024; x += stride) {
        long k = x >> 10, jj = x & 1023;
        g_W1T[x] = (k < 271) ? W1[jj * 271 + k] : 0.f;
    }
    for (long x = i; x < 1024L * 1024; x += stride) {
        long k = x >> 10, jj = x & 1023;
        g_W2T[x] = W2[jj * 1024 + k];
    }
    for (long x = i; x < 1024L * 512; x += stride) {
        long k = x / 512, jj = x - k * 512;
        g_W3T[x] = W3[jj * 1024 + k];
    }
    for (long x = i; x < 512L * 256; x += stride) {
        long k = x >> 8, jj = x & 255;
        g_W4T[x] = W4[jj * 512 + k];
    }
    // first 16 cols: state features (15) + one zero; col 271 zero pad
    for (long x = i; x < (long)BATCH * 16; x += stride) {
        long b = x >> 4, f = x & 15;
        g_xin[b * XIN_LD + f] = (f < 15) ? state[b * 300 + f] : 0.f;
    }
    for (long x = i; x < (long)BATCH; x += stride)
        g_xin[x * XIN_LD + 271] = 0.f;
}

// ---------------------------------------------------------------------------
// GRU: 32 batch rows per CTA, h in SMEM for all 20 steps. 512 threads:
//   jp=tid&127 -> cols (2jp,2jp+1); ty=tid>>7 -> rows ty*8..ty*8+7.
// Hidden-side K loop processes k in PAIRS: LDS.64 broadcast h loads.
// ---------------------------------------------------------------------------
__global__ __launch_bounds__(512, 1) void gru_kernel(
    const float* __restrict__ state,
    const float* __restrict__ b_ih,
    const float* __restrict__ b_hh) {
    __shared__ float h_s[32][256];
    __shared__ float s_s[32][15];
    int tid = threadIdx.x;
    int jp = tid & 127; int j = jp << 1;
    int ty = tid >> 7;  int r0 = ty << 3;
    long b0 = (long)blockIdx.x << 5;

    for (int idx = tid; idx < 32 * 256; idx += 512) ((float*)h_s)[idx] = 0.f;

    u64 bias_r  = *(const u64*)(g_brz + j);
    u64 bias_z  = *(const u64*)(g_brz + 256 + j);
    u64 bias_xn = *(const u64*)(b_ih + 512 + j);
    u64 bias_hn = *(const u64*)(b_hh + 512 + j);

    for (int t = 0; t < 20; t++) {
        __syncthreads();
        if (tid < 480) {
            int rr = tid / 15, ff = tid - rr * 15;
            s_s[rr][ff] = state[(b0 + rr) * 300 + t * 15 + ff];
        }
        __syncthreads();

        u64 accr[8], accz[8], accxn[8], acchn[8];
        #pragma unroll
        for (int i = 0; i < 8; i++) {
            accr[i] = bias_r; accz[i] = bias_z;
            accxn[i] = bias_xn; acchn[i] = bias_hn;
        }
        // input side: K=15 (scalar; small)
        #pragma unroll 3
        for (int k = 0; k < 15; k++) {
            u64 wr = *(const u64*)(g_WihT + k * 768 + j);
            u64 wz = *(const u64*)(g_WihT + k * 768 + 256 + j);
            u64 wn = *(const u64*)(g_WihT + k * 768 + 512 + j);
            #pragma unroll
            for (int i = 0; i < 8; i++) {
                u64 aa = pk2(s_s[r0 + i][k]);
                fma2(accr[i], aa, wr);
                fma2(accz[i], aa, wz);
                fma2(accxn[i], aa, wn);
            }
        }
        // hidden side: K=256, k in pairs (LDS.64 broadcast)
        #pragma unroll 2
        for (int k = 0; k < 256; k += 2) {
            float2 hv[8];
            #pragma unroll
            for (int i = 0; i < 8; i++)
                hv[i] = *(const float2*)&h_s[r0 + i][k];
            #pragma unroll
            for (int q = 0; q < 2; q++) {
                const float* wb = g_WhhT + (k + q) * 768 + j;
                u64 wr = *(const u64*)(wb);
                u64 wz = *(const u64*)(wb + 256);
                u64 wn = *(const u64*)(wb + 512);
                #pragma unroll
                for (int i = 0; i < 8; i++) {
                    u64 aa = pk2(q ? hv[i].y : hv[i].x);
                    fma2(accr[i], aa, wr);
                    fma2(accz[i], aa, wz);
                    fma2(acchn[i], aa, wn);
                }
            }
        }
        __syncthreads();
        #pragma unroll
        for (int i = 0; i < 8; i++) {
            float2 fr = unpk(accr[i]),  fz = unpk(accz[i]);
            float2 fxn = unpk(accxn[i]), fhn = unpk(acchn[i]);
            float h0 = h_s[r0 + i][j], h1 = h_s[r0 + i][j + 1];
            float rr0 = sigf(fr.x), rr1 = sigf(fr.y);
            float zz0 = sigf(fz.x), zz1 = sigf(fz.y);
            float nn0 = tanhf(fxn.x + rr0 * fhn.x);
            float nn1 = tanhf(fxn.y + rr1 * fhn.y);
            h_s[r0 + i][j]     = (1.f - zz0) * nn0 + zz0 * h0;
            h_s[r0 + i][j + 1] = (1.f - zz1) * nn1 + zz1 * h1;
        }
    }
    __syncthreads();
    for (int idx = tid; idx < 32 * 256; idx += 512) {
        int rr = idx >> 8, cc = idx & 255;
        g_xin[(b0 + rr) * XIN_LD + 15 + cc] = h_s[rr][cc];
    }
}

// ---------------------------------------------------------------------------
// MLP layer: Y[M,N] = relu(X[M,K] @ WT + bias). CTA tile 128 rows x 256 cols.
// 512 threads: tx=lane -> 8 cols; ty=warp -> 8 rows. 64 f32x2 accumulators.
// K streamed through SMEM in 64-wide chunks, k processed in pairs.
// Kpad: loop bound (mult of 64, weights zero-padded); Kload: x valid bound.
// ---------------------------------------------------------------------------
__device__ __forceinline__ void mlp_body(
    const float* __restrict__ X, int ldx, int Kpad, int Kload,
    const float* __restrict__ WT, const float* __restrict__ bias,
    float* __restrict__ Y, int N) {
    __shared__ float x_s[128][64];
    int tid = threadIdx.x;
    int tx = tid & 31, ty = tid >> 5;
    int c0 = blockIdx.y * 256 + tx * 8;
    long m0 = (long)blockIdx.x * 128;

    ulonglong2 ba = *(const ulonglong2*)(bias + c0);
    ulonglong2 bb = *(const ulonglong2*)(bias + c0 + 4);
    u64 acc[8][4];
    #pragma unroll
    for (int i = 0; i < 8; i++) {
        acc[i][0] = ba.x; acc[i][1] = ba.y; acc[i][2] = bb.x; acc[i][3] = bb.y;
    }

    for (int kk = 0; kk < Kpad; kk += 64) {
        __syncthreads();
        // fill x tile: 128 rows x 16 float4
        for (int idx = tid; idx < 2048; idx += 512) {
            int rr = idx >> 4, kq = (idx & 15) << 2;
            float4 v = make_float4(0.f, 0.f, 0.f, 0.f);
            if (kk + kq < Kload)
                v = *(const float4*)&X[(size_t)(m0 + rr) * ldx + kk + kq];
            *(float4*)&x_s[rr][kq] = v;
        }
        __syncthreads();
        const float* wbase = WT + (size_t)kk * N + c0;
        #pragma unroll 4
        for (int k = 0; k < 64; k += 2) {
            float2 xv[8];
            #pragma unroll
            for (int i = 0; i < 8; i++)
                xv[i] = *(const float2*)&x_s[ty * 8 + i][k];
            #pragma unroll
            for (int q = 0; q < 2; q++) {
                const float* wp = wbase + (size_t)(k + q) * N;
                ulonglong2 wa = *(const ulonglong2*)(wp);
                ulonglong2 wb = *(const ulonglong2*)(wp + 4);
                #pragma unroll
                for (int i = 0; i < 8; i++) {
                    u64 aa = pk2(q ? xv[i].y : xv[i].x);
                    fma2(acc[i][0], aa, wa.x);
                    fma2(acc[i][1], aa, wa.y);
                    fma2(acc[i][2], aa, wb.x);
                    fma2(acc[i][3], aa, wb.y);
                }
            }
        }
    }
    #pragma unroll
    for (int i = 0; i < 8; i++) {
        long row = m0 + ty * 8 + i;
        float2 v0 = unpk(acc[i][0]), v1 = unpk(acc[i][1]);
        float2 v2 = unpk(acc[i][2]), v3 = unpk(acc[i][3]);
        float4 o0, o1;
        o0.x = fmaxf(v0.x, 0.f); o0.y = fmaxf(v0.y, 0.f);
        o0.z = fmaxf(v1.x, 0.f); o0.w = fmaxf(v1.y, 0.f);
        o1.x = fmaxf(v2.x, 0.f); o1.y = fmaxf(v2.y, 0.f);
        o1.z = fmaxf(v3.x, 0.f); o1.w = fmaxf(v3.y, 0.f);
        *(float4*)&Y[row * N + c0]     = o0;
        *(float4*)&Y[row * N + c0 + 4] = o1;
    }
}

__global__ __launch_bounds__(512, 1) void mlp1_kernel(const float* __restrict__ b1) {
    mlp_body(g_xin, XIN_LD, K1PAD, 272, g_W1T, b1, g_x1, 1024);
}
__global__ __launch_bounds__(512, 1) void mlp2_kernel(const float* __restrict__ b2) {
    mlp_body(g_x1, 1024, 1024, 1024, g_W2T, b2, g_x2, 1024);
}
__global__ __launch_bounds__(512, 1) void mlp3_kernel(const float* __restrict__ b3) {
    mlp_body(g_x2, 1024, 1024, 1024, g_W3T, b3, g_x3, 512);
}
__global__ __launch_bounds__(512, 1) void mlp4_kernel(const float* __restrict__ b4) {
    mlp_body(g_x3, 512, 512, 512, g_W4T, b4, g_x4, 256);
}

// ---------------------------------------------------------------------------
// Head: out[b] = tanh(dot(x4[b], Wp) + bp). One warp per row.
// ---------------------------------------------------------------------------
__global__ void head_kernel(const float* __restrict__ Wp,
                            const float* __restrict__ bp,
                            float* __restrict__ out) {
    __shared__ float wp_s[256];
    int tid = threadIdx.x;
    if (tid < 256) wp_s[tid] = Wp[tid];
    __syncthreads();
    int warp = tid >> 5, lane = tid & 31;
    long b = (long)blockIdx.x * 8 + warp;
    float s = 0.f;
    #pragma unroll
    for (int i = 0; i < 8; i++) {
        int c = lane + 32 * i;
        s += g_x4[b * 256 + c] * wp_s[c];
    }
    #pragma unroll
    for (int o = 16; o; o >>= 1) s += __shfl_xor_sync(0xFFFFFFFFu, s, o);
    if (lane == 0) out[b] = tanhf(s + bp[0]);
}

// ---------------------------------------------------------------------------
extern "C" void kernel_launch(void* const* d_in, const int* in_sizes, int n_in,
                              void* d_out, int out_size) {
    const float* state = (const float*)d_in[0];
    const float* W_ih  = (const float*)d_in[1];
    const float* W_hh  = (const float*)d_in[2];
    const float* b_ih  = (const float*)d_in[3];
    const float* b_hh  = (const float*)d_in[4];
    const float* W1    = (const float*)d_in[5];
    const float* b1    = (const float*)d_in[6];
    const float* W2    = (const float*)d_in[7];
    const float* b2    = (const float*)d_in[8];
    const float* W3    = (const float*)d_in[9];
    const float* b3    = (const float*)d_in[10];
    const float* W4    = (const float*)d_in[11];
    const float* b4    = (const float*)d_in[12];
    const float* Wp    = (const float*)d_in[13];
    const float* bp    = (const float*)d_in[14];
    float* out = (float*)d_out;

    prep_kernel<<<2048, 256>>>(state, W_ih, W_hh, b_ih, b_hh, W1, W2, W3, W4);
    gru_kernel<<<BATCH / 32, 512>>>(state, b_ih, b_hh);
    mlp1_kernel<<<dim3(BATCH / 128, 4), 512>>>(b1);
    mlp2_kernel<<<dim3(BATCH / 128, 4), 512>>>(b2);
    mlp3_kernel<<<dim3(BATCH / 128, 2), 512>>>(b3);
    mlp4_kernel<<<dim3(BATCH / 128, 1), 512>>>(b4);
    head_kernel<<<BATCH / 8, 256>>>(Wp, bp, out);
}

// round 8
// speedup vs baseline: 1.2977x; 1.0858x over previous
#include <cuda_runtime.h>
#include <cuda_bf16.h>

// ---------------------------------------------------------------------------
// Actor: GRU (H=256) over V=20 steps + 4-layer MLP + tanh head. B=16384, F=15.
// f32x2 packed-FFMA; 256-thread CTAs for 2 CTAs/SM (latency overlap across
// CTAs at barriers); register double-buffered MLP tiles; GRU state prefetch.
// ---------------------------------------------------------------------------

#define BATCH 16384
typedef unsigned long long u64;

#define XIN_LD 320              // [state15 | h256 | zero-pad to 320]
#define K1PAD 320

__device__ __align__(16) float g_WihT[15 * 768];
__device__ __align__(16) float g_WhhT[256 * 768];
__device__ __align__(16) float g_brz[512];
__device__ __align__(16) float g_W1T[K1PAD * 1024];
__device__ __align__(16) float g_W2T[1024 * 1024];
__device__ __align__(16) float g_W3T[1024 * 512];
__device__ __align__(16) float g_W4T[512 * 256];
__device__ __align__(16) float g_xin[BATCH * XIN_LD];
__device__ __align__(16) float g_x1[BATCH * 1024];
__device__ __align__(16) float g_x2[BATCH * 1024];
__device__ __align__(16) float g_x3[BATCH * 512];
__device__ __align__(16) float g_x4[BATCH * 256];

// ---- packed f32x2 helpers ----
__device__ __forceinline__ u64 pk2(float a) {
    u64 r; asm("mov.b64 %0, {%1, %1};" : "=l"(r) : "f"(a)); return r;
}
__device__ __forceinline__ void fma2(u64& d, u64 a, u64 b) {
    asm("fma.rn.f32x2 %0, %1, %2, %0;" : "+l"(d) : "l"(a), "l"(b));
}
__device__ __forceinline__ float2 unpk(u64 v) {
    float x, y; asm("mov.b64 {%0, %1}, %2;" : "=f"(x), "=f"(y) : "l"(v));
    float2 f; f.x = x; f.y = y; return f;
}
__device__ __forceinline__ float sigf(float x) {
    return 1.f / (1.f + __expf(-x));
}

// ---------------------------------------------------------------------------
// Prep: k-major transposes (+zero padding), combined r/z biases, xin setup.
// ---------------------------------------------------------------------------
__global__ void prep_kernel(const float* __restrict__ state,
                            const float* __restrict__ W_ih,
                            const float* __restrict__ W_hh,
                            const float* __restrict__ b_ih,
                            const float* __restrict__ b_hh,
                            const float* __restrict__ W1,
                            const float* __restrict__ W2,
                            const float* __restrict__ W3,
                            const float* __restrict__ W4) {
    long i = (long)blockIdx.x * blockDim.x + threadIdx.x;
    long stride = (long)gridDim.x * blockDim.x;
    for (long x = i; x < 15L * 768; x += stride) {
        long k = x / 768, jj = x - k * 768;
        g_WihT[x] = W_ih[jj * 15 + k];
    }
    for (long x = i; x < 256L * 768; x += stride) {
        long k = x / 768, jj = x - k * 768;
        g_WhhT[x] = W_hh[jj * 256 + k];
    }
    for (long x = i; x < 512; x += stride) g_brz[x] = b_ih[x] + b_hh[x];
    for (long x = i; x < (long)K1PAD * 1024; x += stride) {
        long k = x >> 10, jj = x & 1023;
        g_W1T[x] = (k < 271) ? W1[jj * 271 + k] : 0.f;
    }
    for (long x = i; x < 1024L * 1024; x += stride) {
        long k = x >> 10, jj = x & 1023;
        g_W2T[x] = W2[jj * 1024 + k];
    }
    for (long x = i; x < 1024L * 512; x += stride) {
        long k = x / 512, jj = x - k * 512;
        g_W3T[x] = W3[jj * 1024 + k];
    }
    for (long x = i; x < 512L * 256; x += stride) {
        long k = x >> 8, jj = x & 255;
        g_W4T[x] = W4[jj * 512 + k];
    }
    // cols 0..15: state features (15) + zero
    for (long x = i; x < (long)BATCH * 16; x += stride) {
        long b = x >> 4, f = x & 15;
        g_xin[b * XIN_LD + f] = (f < 15) ? state[b * 300 + f] : 0.f;
    }
    // cols 256..319 zero (GRU later overwrites 256..270; 271..319 stay zero)
    for (long x = i; x < (long)BATCH * 64; x += stride) {
        long b = x >> 6, c = 256 + (x & 63);
        g_xin[b * XIN_LD + c] = 0.f;
    }
}

// ---------------------------------------------------------------------------
// GRU: 16 batch rows per CTA, 256 threads (2 CTAs/SM). h in SMEM all 20 steps.
//   jp=tid&127 -> cols (2jp,2jp+1); ty=tid>>7 in {0,1} -> rows ty*8..ty*8+7.
// Per thread: 8 rows x {r,z,xn,hn} f32x2 accumulators. Next-step state is
// prefetched into registers during the hidden-side loop.
// ---------------------------------------------------------------------------
__global__ __launch_bounds__(256, 2) void gru_kernel(
    const float* __restrict__ state,
    const float* __restrict__ b_ih,
    const float* __restrict__ b_hh) {
    __shared__ float h_s[16][256];
    __shared__ float s_s[2][16][16];
    int tid = threadIdx.x;
    int jp = tid & 127; int j = jp << 1;
    int ty = tid >> 7;  int r0 = ty << 3;
    long b0 = (long)blockIdx.x << 4;

    for (int idx = tid; idx < 16 * 256; idx += 256) ((float*)h_s)[idx] = 0.f;

    int srr = tid / 15, sff = tid - srr * 15;
    bool sact = tid < 240;
    if (sact) s_s[0][srr][sff] = state[(b0 + srr) * 300 + sff];

    u64 bias_r  = *(const u64*)(g_brz + j);
    u64 bias_z  = *(const u64*)(g_brz + 256 + j);
    u64 bias_xn = *(const u64*)(b_ih + 512 + j);
    u64 bias_hn = *(const u64*)(b_hh + 512 + j);
    __syncthreads();

    for (int t = 0; t < 20; t++) {
        int cur = t & 1;
        u64 accr[8], accz[8], accxn[8], acchn[8];
        #pragma unroll
        for (int i = 0; i < 8; i++) {
            accr[i] = bias_r; accz[i] = bias_z;
            accxn[i] = bias_xn; acchn[i] = bias_hn;
        }
        // input side: K=15
        #pragma unroll 3
        for (int k = 0; k < 15; k++) {
            u64 wr = *(const u64*)(g_WihT + k * 768 + j);
            u64 wz = *(const u64*)(g_WihT + k * 768 + 256 + j);
            u64 wn = *(const u64*)(g_WihT + k * 768 + 512 + j);
            #pragma unroll
            for (int i = 0; i < 8; i++) {
                u64 aa = pk2(s_s[cur][r0 + i][k]);
                fma2(accr[i], aa, wr);
                fma2(accz[i], aa, wz);
                fma2(accxn[i], aa, wn);
            }
        }
        // prefetch next step's state (hidden loop hides DRAM latency)
        float sv = 0.f;
        if (sact && t < 19) sv = state[(b0 + srr) * 300 + (t + 1) * 15 + sff];

        // hidden side: K=256, k-pairs via LDS.64 broadcast
        #pragma unroll 4
        for (int k = 0; k < 256; k += 2) {
            float2 hv[8];
            #pragma unroll
            for (int i = 0; i < 8; i++)
                hv[i] = *(const float2*)&h_s[r0 + i][k];
            #pragma unroll
            for (int q = 0; q < 2; q++) {
                const float* wb = g_WhhT + (k + q) * 768 + j;
                u64 wr = *(const u64*)(wb);
                u64 wz = *(const u64*)(wb + 256);
                u64 wn = *(const u64*)(wb + 512);
                #pragma unroll
                for (int i = 0; i < 8; i++) {
                    u64 aa = pk2(q ? hv[i].y : hv[i].x);
                    fma2(accr[i], aa, wr);
                    fma2(accz[i], aa, wz);
                    fma2(acchn[i], aa, wn);
                }
            }
        }
        if (sact && t < 19) s_s[cur ^ 1][srr][sff] = sv;
        __syncthreads();   // hidden reads of h_s done; s_s[next] written
        #pragma unroll
        for (int i = 0; i < 8; i++) {
            float2 fr = unpk(accr[i]),  fz = unpk(accz[i]);
            float2 fxn = unpk(accxn[i]), fhn = unpk(acchn[i]);
            float h0 = h_s[r0 + i][j], h1 = h_s[r0 + i][j + 1];
            float rr0 = sigf(fr.x), rr1 = sigf(fr.y);
            float zz0 = sigf(fz.x), zz1 = sigf(fz.y);
            float nn0 = tanhf(fxn.x + rr0 * fhn.x);
            float nn1 = tanhf(fxn.y + rr1 * fhn.y);
            h_s[r0 + i][j]     = (1.f - zz0) * nn0 + zz0 * h0;
            h_s[r0 + i][j + 1] = (1.f - zz1) * nn1 + zz1 * h1;
        }
        __syncthreads();   // new h visible before next step's reads
    }
    for (int idx = tid; idx < 16 * 256; idx += 256) {
        int rr = idx >> 8, cc = idx & 255;
        g_xin[(b0 + rr) * XIN_LD + 15 + cc] = h_s[rr][cc];
    }
}

// ---------------------------------------------------------------------------
// MLP layer: Y = relu(X @ WT + bias). CTA tile 64 rows x 256 cols, 256 thr
// (2 CTAs/SM). tx=lane -> 8 cols, ty=warp -> 8 rows. K in 64-chunks with
// register double-buffering of the x tile (LDG overlapped with compute).
// K must be a multiple of 64 (inputs zero-padded).
// ---------------------------------------------------------------------------
__device__ __forceinline__ void mlp_body(
    const float* __restrict__ X, int ldx, int K,
    const float* __restrict__ WT, const float* __restrict__ bias,
    float* __restrict__ Y, int N) {
    __shared__ float x_s[64][64];
    int tid = threadIdx.x;
    int tx = tid & 31, ty = tid >> 5;
    int c0 = blockIdx.y * 256 + tx * 8;
    long m0 = (long)blockIdx.x * 64;

    ulonglong2 ba = *(const ulonglong2*)(bias + c0);
    ulonglong2 bb = *(const ulonglong2*)(bias + c0 + 4);
    u64 acc[8][4];
    #pragma unroll
    for (int i = 0; i < 8; i++) {
        acc[i][0] = ba.x; acc[i][1] = ba.y; acc[i][2] = bb.x; acc[i][3] = bb.y;
    }

    // fill indices: 64 rows x 16 float4; 4 float4 per thread
    int frow[4], fc4[4];
    #pragma unroll
    for (int p = 0; p < 4; p++) {
        int idx = tid + 256 * p;
        frow[p] = idx >> 4; fc4[p] = (idx & 15) << 2;
    }
    float4 pf[4];
    #pragma unroll
    for (int p = 0; p < 4; p++)
        pf[p] = *(const float4*)&X[(size_t)(m0 + frow[p]) * ldx + fc4[p]];
    #pragma unroll
    for (int p = 0; p < 4; p++)
        *(float4*)&x_s[frow[p]][fc4[p]] = pf[p];
    __syncthreads();

    int nc = K >> 6;
    for (int c = 0; c < nc; c++) {
        float4 nf[4];
        if (c + 1 < nc) {
            int kk = (c + 1) << 6;
            #pragma unroll
            for (int p = 0; p < 4; p++)
                nf[p] = *(const float4*)&X[(size_t)(m0 + frow[p]) * ldx + kk + fc4[p]];
        }
        const float* wbase = WT + ((size_t)c << 6) * N + c0;
        #pragma unroll 4
        for (int k = 0; k < 64; k += 2) {
            float2 xv[8];
            #pragma unroll
            for (int i = 0; i < 8; i++)
                xv[i] = *(const float2*)&x_s[ty * 8 + i][k];
            #pragma unroll
            for (int q = 0; q < 2; q++) {
                const float* wp = wbase + (size_t)(k + q) * N;
                ulonglong2 wa = *(const ulonglong2*)(wp);
                ulonglong2 wb = *(const ulonglong2*)(wp + 4);
                #pragma unroll
                for (int i = 0; i < 8; i++) {
                    u64 aa = pk2(q ? xv[i].y : xv[i].x);
                    fma2(acc[i][0], aa, wa.x);
                    fma2(acc[i][1], aa, wa.y);
                    fma2(acc[i][2], aa, wb.x);
                    fma2(acc[i][3], aa, wb.y);
                }
            }
        }
        __syncthreads();           // all reads of x_s done
        if (c + 1 < nc) {
            #pragma unroll
            for (int p = 0; p < 4; p++)
                *(float4*)&x_s[frow[p]][fc4[p]] = nf[p];
            __syncthreads();       // new tile visible
        }
    }
    #pragma unroll
    for (int i = 0; i < 8; i++) {
        long row = m0 + ty * 8 + i;
        float2 v0 = unpk(acc[i][0]), v1 = unpk(acc[i][1]);
        float2 v2 = unpk(acc[i][2]), v3 = unpk(acc[i][3]);
        float4 o0, o1;
        o0.x = fmaxf(v0.x, 0.f); o0.y = fmaxf(v0.y, 0.f);
        o0.z = fmaxf(v1.x, 0.f); o0.w = fmaxf(v1.y, 0.f);
        o1.x = fmaxf(v2.x, 0.f); o1.y = fmaxf(v2.y, 0.f);
        o1.z = fmaxf(v3.x, 0.f); o1.w = fmaxf(v3.y, 0.f);
        *(float4*)&Y[row * N + c0]     = o0;
        *(float4*)&Y[row * N + c0 + 4] = o1;
    }
}

__global__ __launch_bounds__(256, 2) void mlp1_kernel(const float* __restrict__ b1) {
    mlp_body(g_xin, XIN_LD, K1PAD, g_W1T, b1, g_x1, 1024);
}
__global__ __launch_bounds__(256, 2) void mlp2_kernel(const float* __restrict__ b2) {
    mlp_body(g_x1, 1024, 1024, g_W2T, b2, g_x2, 1024);
}
__global__ __launch_bounds__(256, 2) void mlp3_kernel(const float* __restrict__ b3) {
    mlp_body(g_x2, 1024, 1024, g_W3T, b3, g_x3, 512);
}
__global__ __launch_bounds__(256, 2) void mlp4_kernel(const float* __restrict__ b4) {
    mlp_body(g_x3, 512, 512, g_W4T, b4, g_x4, 256);
}

// ---------------------------------------------------------------------------
// Head: out[b] = tanh(dot(x4[b], Wp) + bp). One warp per row.
// ---------------------------------------------------------------------------
__global__ void head_kernel(const float* __restrict__ Wp,
                            const float* __restrict__ bp,
                            float* __restrict__ out) {
    __shared__ float wp_s[256];
    int tid = threadIdx.x;
    if (tid < 256) wp_s[tid] = Wp[tid];
    __syncthreads();
    int warp = tid >> 5, lane = tid & 31;
    long b = (long)blockIdx.x * 8 + warp;
    float s = 0.f;
    #pragma unroll
    for (int i = 0; i < 8; i++) {
        int c = lane + 32 * i;
        s += g_x4[b * 256 + c] * wp_s[c];
    }
    #pragma unroll
    for (int o = 16; o; o >>= 1) s += __shfl_xor_sync(0xFFFFFFFFu, s, o);
    if (lane == 0) out[b] = tanhf(s + bp[0]);
}

// ---------------------------------------------------------------------------
extern "C" void kernel_launch(void* const* d_in, const int* in_sizes, int n_in,
                              void* d_out, int out_size) {
    const float* state = (const float*)d_in[0];
    const float* W_ih  = (const float*)d_in[1];
    const float* W_hh  = (const float*)d_in[2];
    const float* b_ih  = (const float*)d_in[3];
    const float* b_hh  = (const float*)d_in[4];
    const float* W1    = (const float*)d_in[5];
    const float* b1    = (const float*)d_in[6];
    const float* W2    = (const float*)d_in[7];
    const float* b2    = (const float*)d_in[8];
    const float* W3    = (const float*)d_in[9];
    const float* b3    = (const float*)d_in[10];
    const float* W4    = (const float*)d_in[11];
    const float* b4    = (const float*)d_in[12];
    const float* Wp    = (const float*)d_in[13];
    const float* bp    = (const float*)d_in[14];
    float* out = (float*)d_out;

    prep_kernel<<<2048, 256>>>(state, W_ih, W_hh, b_ih, b_hh, W1, W2, W3, W4);
    gru_kernel<<<BATCH / 16, 256>>>(state, b_ih, b_hh);
    mlp1_kernel<<<dim3(BATCH / 64, 4), 256>>>(b1);
    mlp2_kernel<<<dim3(BATCH / 64, 4), 256>>>(b2);
    mlp3_kernel<<<dim3(BATCH / 64, 2), 256>>>(b3);
    mlp4_kernel<<<dim3(BATCH / 64, 1), 256>>>(b4);
    head_kernel<<<BATCH / 8, 256>>>(Wp, bp, out);
}

// round 14
// speedup vs baseline: 1.6117x; 1.2420x over previous
#include <cuda_runtime.h>
#include <cstdint>

// ---------------------------------------------------------------------------
// Actor: GRU (H=256, fp32x2 FFMA, SMEM-resident h) + 4-layer MLP on
// mma.sync.m16n8k8 tf32 with 3xTF32 error compensation (near-fp32 accuracy)
// + tanh head. B=16384, F=15.
// ---------------------------------------------------------------------------

#define BATCH 16384
typedef unsigned long long u64;

#define XIN_LD 320              // [state15 | h256 | zero-pad]
#define K1 288                  // layer-1 K padded to 9x32

__device__ __align__(16) float g_WihT[15 * 768];
__device__ __align__(16) float g_WhhT[256 * 768];
__device__ __align__(16) float g_brz[512];
// tf32 hi/lo split weights, [N][K] row-major
__device__ __align__(16) float g_W1h[1024 * K1],  g_W1l[1024 * K1];
__device__ __align__(16) float g_W2h[1024 * 1024], g_W2l[1024 * 1024];
__device__ __align__(16) float g_W3h[512 * 1024],  g_W3l[512 * 1024];
__device__ __align__(16) float g_W4h[256 * 512],   g_W4l[256 * 512];
__device__ __align__(16) float g_xin[BATCH * XIN_LD];
__device__ __align__(16) float g_x1[BATCH * 1024];
__device__ __align__(16) float g_x2[BATCH * 1024];
__device__ __align__(16) float g_x3[BATCH * 512];
__device__ __align__(16) float g_x4[BATCH * 256];

// ---- packed f32x2 helpers (GRU) ----
__device__ __forceinline__ u64 pk2(float a) {
    u64 r; asm("mov.b64 %0, {%1, %1};" : "=l"(r) : "f"(a)); return r;
}
__device__ __forceinline__ void fma2(u64& d, u64 a, u64 b) {
    asm("fma.rn.f32x2 %0, %1, %2, %0;" : "+l"(d) : "l"(a), "l"(b));
}
__device__ __forceinline__ float2 unpk(u64 v) {
    float x, y; asm("mov.b64 {%0, %1}, %2;" : "=f"(x), "=f"(y) : "l"(v));
    float2 f; f.x = x; f.y = y; return f;
}
__device__ __forceinline__ float sigf(float x) { return 1.f / (1.f + __expf(-x)); }

// tf32 round-to-nearest (unbiased)
__device__ __forceinline__ float tf32r(float x) {
    uint32_t r; asm("cvt.rna.tf32.f32 %0, %1;" : "=r"(r) : "f"(x));
    return __uint_as_float(r);
}

// ---------------------------------------------------------------------------
// Prep: GRU transposes + combined r/z biases; hi/lo split MLP weights;
// xin setup (full fp32; zero padding).
// ---------------------------------------------------------------------------
__global__ void prep_kernel(const float* __restrict__ state,
                            const float* __restrict__ W_ih,
                            const float* __restrict__ W_hh,
                            const float* __restrict__ b_ih,
                            const float* __restrict__ b_hh,
                            const float* __restrict__ W1,
                            const float* __restrict__ W2,
                            const float* __restrict__ W3,
                            const float* __restrict__ W4) {
    long i = (long)blockIdx.x * blockDim.x + threadIdx.x;
    long stride = (long)gridDim.x * blockDim.x;
    for (long x = i; x < 15L * 768; x += stride) {
        long k = x / 768, jj = x - k * 768;
        g_WihT[x] = W_ih[jj * 15 + k];
    }
    for (long x = i; x < 256L * 768; x += stride) {
        long k = x / 768, jj = x - k * 768;
        g_WhhT[x] = W_hh[jj * 256 + k];
    }
    for (long x = i; x < 512; x += stride) g_brz[x] = b_ih[x] + b_hh[x];
    for (long x = i; x < 1024L * K1; x += stride) {
        long n = x / K1, k = x - n * K1;
        float w = (k < 271) ? W1[n * 271 + k] : 0.f;
        float h = tf32r(w);
        g_W1h[x] = h; g_W1l[x] = tf32r(w - h);
    }
    for (long x = i; x < 1024L * 1024; x += stride) {
        float w = W2[x], h = tf32r(w);
        g_W2h[x] = h; g_W2l[x] = tf32r(w - h);
    }
    for (long x = i; x < 512L * 1024; x += stride) {
        float w = W3[x], h = tf32r(w);
        g_W3h[x] = h; g_W3l[x] = tf32r(w - h);
    }
    for (long x = i; x < 256L * 512; x += stride) {
        float w = W4[x], h = tf32r(w);
        g_W4h[x] = h; g_W4l[x] = tf32r(w - h);
    }
    for (long x = i; x < (long)BATCH * 16; x += stride) {
        long b = x >> 4, f = x & 15;
        g_xin[b * XIN_LD + f] = (f < 15) ? state[b * 300 + f] : 0.f;
    }
    for (long x = i; x < (long)BATCH * 64; x += stride) {
        long b = x >> 6, c = 256 + (x & 63);
        g_xin[b * XIN_LD + c] = 0.f;
    }
}

// ---------------------------------------------------------------------------
// GRU (fp32x2): 16 rows/CTA, 256 threads, 2 CTAs/SM, h in SMEM all 20 steps.
// (The 5507us passing version; h written full fp32.)
// ---------------------------------------------------------------------------
__global__ __launch_bounds__(256, 2) void gru_kernel(
    const float* __restrict__ state,
    const float* __restrict__ b_ih,
    const float* __restrict__ b_hh) {
    __shared__ float h_s[16][256];
    __shared__ float s_s[2][16][16];
    int tid = threadIdx.x;
    int jp = tid & 127; int j = jp << 1;
    int ty = tid >> 7;  int r0 = ty << 3;
    long b0 = (long)blockIdx.x << 4;

    for (int idx = tid; idx < 16 * 256; idx += 256) ((float*)h_s)[idx] = 0.f;

    int srr = tid / 15, sff = tid - srr * 15;
    bool sact = tid < 240;
    if (sact) s_s[0][srr][sff] = state[(b0 + srr) * 300 + sff];

    u64 bias_r  = *(const u64*)(g_brz + j);
    u64 bias_z  = *(const u64*)(g_brz + 256 + j);
    u64 bias_xn = *(const u64*)(b_ih + 512 + j);
    u64 bias_hn = *(const u64*)(b_hh + 512 + j);
    __syncthreads();

    for (int t = 0; t < 20; t++) {
        int cur = t & 1;
        u64 accr[8], accz[8], accxn[8], acchn[8];
        #pragma unroll
        for (int i = 0; i < 8; i++) {
            accr[i] = bias_r; accz[i] = bias_z;
            accxn[i] = bias_xn; acchn[i] = bias_hn;
        }
        #pragma unroll 3
        for (int k = 0; k < 15; k++) {
            u64 wr = *(const u64*)(g_WihT + k * 768 + j);
            u64 wz = *(const u64*)(g_WihT + k * 768 + 256 + j);
            u64 wn = *(const u64*)(g_WihT + k * 768 + 512 + j);
            #pragma unroll
            for (int i = 0; i < 8; i++) {
                u64 aa = pk2(s_s[cur][r0 + i][k]);
                fma2(accr[i], aa, wr);
                fma2(accz[i], aa, wz);
                fma2(accxn[i], aa, wn);
            }
        }
        float sv = 0.f;
        if (sact && t < 19) sv = state[(b0 + srr) * 300 + (t + 1) * 15 + sff];

        #pragma unroll 4
        for (int k = 0; k < 256; k += 2) {
            float2 hv[8];
            #pragma unroll
            for (int i = 0; i < 8; i++)
                hv[i] = *(const float2*)&h_s[r0 + i][k];
            #pragma unroll
            for (int q = 0; q < 2; q++) {
                const float* wb = g_WhhT + (k + q) * 768 + j;
                u64 wr = *(const u64*)(wb);
                u64 wz = *(const u64*)(wb + 256);
                u64 wn = *(const u64*)(wb + 512);
                #pragma unroll
                for (int i = 0; i < 8; i++) {
                    u64 aa = pk2(q ? hv[i].y : hv[i].x);
                    fma2(accr[i], aa, wr);
                    fma2(accz[i], aa, wz);
                    fma2(acchn[i], aa, wn);
                }
            }
        }
        if (sact && t < 19) s_s[cur ^ 1][srr][sff] = sv;
        __syncthreads();
        #pragma unroll
        for (int i = 0; i < 8; i++) {
            float2 fr = unpk(accr[i]),  fz = unpk(accz[i]);
            float2 fxn = unpk(accxn[i]), fhn = unpk(acchn[i]);
            float h0 = h_s[r0 + i][j], h1 = h_s[r0 + i][j + 1];
            float rr0 = sigf(fr.x), rr1 = sigf(fr.y);
            float zz0 = sigf(fz.x), zz1 = sigf(fz.y);
            float nn0 = tanhf(fxn.x + rr0 * fhn.x);
            float nn1 = tanhf(fxn.y + rr1 * fhn.y);
            h_s[r0 + i][j]     = (1.f - zz0) * nn0 + zz0 * h0;
            h_s[r0 + i][j + 1] = (1.f - zz1) * nn1 + zz1 * h1;
        }
        __syncthreads();
    }
    for (int idx = tid; idx < 16 * 256; idx += 256) {
        int rr = idx >> 8, cc = idx & 255;
        g_xin[(b0 + rr) * XIN_LD + 15 + cc] = h_s[rr][cc];
    }
}

// ---------------------------------------------------------------------------
// MLP via 3xTF32 mma.sync m16n8k8. CTA tile 128x128, 8 warps, warp tile
// 32x64. K in 32-chunks; hi/lo SMEM tiles, row stride 36 (conflict-free).
// d += Ah*Bl + Al*Bh + Ah*Bh  (near-fp32 accuracy).
// ---------------------------------------------------------------------------
#define TS (128 * 36)
#define MLP_SMEM (4 * TS * 4)

template <int NCH>
__device__ __forceinline__ void mlp_mma_body(
    const float* __restrict__ X, int ldx,
    const float* __restrict__ Wh, const float* __restrict__ Wl, int ldw,
    const float* __restrict__ bias,
    float* __restrict__ Y, int N, bool relu) {
    extern __shared__ float sm[];
    float* xh = sm;            // 128x36 hi
    float* xl = sm + TS;       // 128x36 lo
    float* wh = sm + 2 * TS;
    float* wl = sm + 3 * TS;
    int tid = threadIdx.x;
    int lane = tid & 31, wid = tid >> 5;
    int wm = wid >> 1, wn = wid & 1;
    int g = lane >> 2, cq = lane & 3;
    long m0 = (long)blockIdx.x * 128;
    int n0 = blockIdx.y * 128;

    float d[2][8][4];
    #pragma unroll
    for (int jb = 0; jb < 8; jb++) {
        float2 bb = *(const float2*)&bias[n0 + 64 * wn + 8 * jb + 2 * cq];
        #pragma unroll
        for (int i = 0; i < 2; i++) {
            d[i][jb][0] = bb.x; d[i][jb][1] = bb.y;
            d[i][jb][2] = bb.x; d[i][jb][3] = bb.y;
        }
    }

    for (int ch = 0; ch < NCH; ch++) {
        int kk = ch * 32;
        __syncthreads();
        #pragma unroll
        for (int p = 0; p < 4; p++) {
            int idx = tid + 256 * p;
            int r = idx >> 3, q = idx & 7;
            float4 xv = *(const float4*)&X[(size_t)(m0 + r) * ldx + kk + 4 * q];
            float4 hv, lv;
            hv.x = tf32r(xv.x); lv.x = tf32r(xv.x - hv.x);
            hv.y = tf32r(xv.y); lv.y = tf32r(xv.y - hv.y);
            hv.z = tf32r(xv.z); lv.z = tf32r(xv.z - hv.z);
            hv.w = tf32r(xv.w); lv.w = tf32r(xv.w - hv.w);
            *(float4*)&xh[r * 36 + 4 * q] = hv;
            *(float4*)&xl[r * 36 + 4 * q] = lv;
            *(float4*)&wh[r * 36 + 4 * q] =
                *(const float4*)&Wh[(size_t)(n0 + r) * ldw + kk + 4 * q];
            *(float4*)&wl[r * 36 + 4 * q] =
                *(const float4*)&Wl[(size_t)(n0 + r) * ldw + kk + 4 * q];
        }
        __syncthreads();
        #pragma unroll
        for (int kb = 0; kb < 4; kb++) {
            uint32_t ah[2][4], al[2][4];
            #pragma unroll
            for (int i = 0; i < 2; i++) {
                int ra = (32 * wm + 16 * i + g) * 36 + 8 * kb + cq;
                int rb = ra + 8 * 36;
                ah[i][0] = __float_as_uint(xh[ra]);
                ah[i][1] = __float_as_uint(xh[rb]);
                ah[i][2] = __float_as_uint(xh[ra + 4]);
                ah[i][3] = __float_as_uint(xh[rb + 4]);
                al[i][0] = __float_as_uint(xl[ra]);
                al[i][1] = __float_as_uint(xl[rb]);
                al[i][2] = __float_as_uint(xl[ra + 4]);
                al[i][3] = __float_as_uint(xl[rb + 4]);
            }
            #pragma unroll
            for (int jb = 0; jb < 8; jb++) {
                int rw = (64 * wn + 8 * jb + g) * 36 + 8 * kb + cq;
                uint32_t bh0 = __float_as_uint(wh[rw]);
                uint32_t bh1 = __float_as_uint(wh[rw + 4]);
                uint32_t bl0 = __float_as_uint(wl[rw]);
                uint32_t bl1 = __float_as_uint(wl[rw + 4]);
                #pragma unroll
                for (int i = 0; i < 2; i++) {
                    #define MMA_(A0,A1,A2,A3,B0,B1) \
                        asm volatile( \
                            "mma.sync.aligned.m16n8k8.row.col.f32.tf32.tf32.f32 " \
                            "{%0,%1,%2,%3}, {%4,%5,%6,%7}, {%8,%9}, {%0,%1,%2,%3};" \
                            : "+f"(d[i][jb][0]), "+f"(d[i][jb][1]), \
                              "+f"(d[i][jb][2]), "+f"(d[i][jb][3]) \
                            : "r"(A0), "r"(A1), "r"(A2), "r"(A3), "r"(B0), "r"(B1))
                    MMA_(al[i][0], al[i][1], al[i][2], al[i][3], bh0, bh1);
                    MMA_(ah[i][0], ah[i][1], ah[i][2], ah[i][3], bl0, bl1);
                    MMA_(ah[i][0], ah[i][1], ah[i][2], ah[i][3], bh0, bh1);
                    #undef MMA_
                }
            }
        }
    }
    #pragma unroll
    for (int i = 0; i < 2; i++) {
        long rg = m0 + 32 * wm + 16 * i;
        #pragma unroll
        for (int jb = 0; jb < 8; jb++) {
            int col = n0 + 64 * wn + 8 * jb + 2 * cq;
            float2 v0, v1;
            v0.x = d[i][jb][0]; v0.y = d[i][jb][1];
            v1.x = d[i][jb][2]; v1.y = d[i][jb][3];
            if (relu) {
                v0.x = fmaxf(v0.x, 0.f); v0.y = fmaxf(v0.y, 0.f);
                v1.x = fmaxf(v1.x, 0.f); v1.y = fmaxf(v1.y, 0.f);
            }
            *(float2*)&Y[(size_t)(rg + g) * N + col]     = v0;
            *(float2*)&Y[(size_t)(rg + 8 + g) * N + col] = v1;
        }
    }
}

__global__ __launch_bounds__(256, 2) void mlp1m(const float* __restrict__ b1) {
    mlp_mma_body<K1 / 32>(g_xin, XIN_LD, g_W1h, g_W1l, K1, b1, g_x1, 1024, true);
}
__global__ __launch_bounds__(256, 2) void mlp2m(const float* __restrict__ b2) {
    mlp_mma_body<32>(g_x1, 1024, g_W2h, g_W2l, 1024, b2, g_x2, 1024, true);
}
__global__ __launch_bounds__(256, 2) void mlp3m(const float* __restrict__ b3) {
    mlp_mma_body<32>(g_x2, 1024, g_W3h, g_W3l, 1024, b3, g_x3, 512, true);
}
__global__ __launch_bounds__(256, 2) void mlp4m(const float* __restrict__ b4) {
    mlp_mma_body<16>(g_x3, 512, g_W4h, g_W4l, 512, b4, g_x4, 256, true);
}

// ---------------------------------------------------------------------------
// Head: out[b] = tanh(dot(x4[b], Wp) + bp). One warp per row.
// ---------------------------------------------------------------------------
__global__ void head_kernel(const float* __restrict__ Wp,
                            const float* __restrict__ bp,
                            float* __restrict__ out) {
    __shared__ float wp_s[256];
    int tid = threadIdx.x;
    if (tid < 256) wp_s[tid] = Wp[tid];
    __syncthreads();
    int warp = tid >> 5, lane = tid & 31;
    long b = (long)blockIdx.x * 8 + warp;
    float s = 0.f;
    #pragma unroll
    for (int i = 0; i < 8; i++) {
        int c = lane + 32 * i;
        s += g_x4[b * 256 + c] * wp_s[c];
    }
    #pragma unroll
    for (int o = 16; o; o >>= 1) s += __shfl_xor_sync(0xFFFFFFFFu, s, o);
    if (lane == 0) out[b] = tanhf(s + bp[0]);
}

// ---------------------------------------------------------------------------
extern "C" void kernel_launch(void* const* d_in, const int* in_sizes, int n_in,
                              void* d_out, int out_size) {
    const float* state = (const float*)d_in[0];
    const float* W_ih  = (const float*)d_in[1];
    const float* W_hh  = (const float*)d_in[2];
    const float* b_ih  = (const float*)d_in[3];
    const float* b_hh  = (const float*)d_in[4];
    const float* W1    = (const float*)d_in[5];
    const float* b1    = (const float*)d_in[6];
    const float* W2    = (const float*)d_in[7];
    const float* b2    = (const float*)d_in[8];
    const float* W3    = (const float*)d_in[9];
    const float* b3    = (const float*)d_in[10];
    const float* W4    = (const float*)d_in[11];
    const float* b4    = (const float*)d_in[12];
    const float* Wp    = (const float*)d_in[13];
    const float* bp    = (const float*)d_in[14];
    float* out = (float*)d_out;

    cudaFuncSetAttribute(mlp1m, cudaFuncAttributeMaxDynamicSharedMemorySize, MLP_SMEM);
    cudaFuncSetAttribute(mlp2m, cudaFuncAttributeMaxDynamicSharedMemorySize, MLP_SMEM);
    cudaFuncSetAttribute(mlp3m, cudaFuncAttributeMaxDynamicSharedMemorySize, MLP_SMEM);
    cudaFuncSetAttribute(mlp4m, cudaFuncAttributeMaxDynamicSharedMemorySize, MLP_SMEM);

    prep_kernel<<<2048, 256>>>(state, W_ih, W_hh, b_ih, b_hh, W1, W2, W3, W4);
    gru_kernel<<<BATCH / 16, 256>>>(state, b_ih, b_hh);
    mlp1m<<<dim3(BATCH / 128, 8), 256, MLP_SMEM>>>(b1);
    mlp2m<<<dim3(BATCH / 128, 8), 256, MLP_SMEM>>>(b2);
    mlp3m<<<dim3(BATCH / 128, 4), 256, MLP_SMEM>>>(b3);
    mlp4m<<<dim3(BATCH / 128, 2), 256, MLP_SMEM>>>(b4);
    head_kernel<<<BATCH / 8, 256>>>(Wp, bp, out);
}